// round 15
// baseline (speedup 1.0000x reference)
#include <cuda_runtime.h>
#include <cuda_bf16.h>
#include <cstdint>

#define VOCAB  50257
#define VPAD   50304          // 1572 * 32, 786 * 64
#define DMODEL 768
#define MTOT   4096           // B*S
#define SEQ    2048

#define BM 128
#define BN 64
#define BK 64
#define STAGES 3
#define NKC (DMODEL / BK)                  // 12
#define A_TILE_BYTES (BM * BK * 2)         // 16384
#define B_TILE_BYTES (BN * BK * 2)         // 8192
#define STAGE_BYTES (A_TILE_BYTES + B_TILE_BYTES)  // 24576
#define SMEM_BYTES (STAGES * STAGE_BYTES)  // 73728 -> 3 CTAs/SM

// GEMM split: G1 = first NT1 n-tiles (32*111 = 3552 CTAs = exactly 8 waves of 444)
#define NT    (VPAD / BN)                  // 786
#define NT1   111
#define NT2   (NT - NT1)                   // 675

// packw split: v-tiles of 32 rows; G1 needs v < NT1*64 = 7104 -> 222 v-tiles
#define NKB   (DMODEL / 64)                // 12
#define NVB   (VPAD / 32)                  // 1572
#define NVB1  (NT1 * 64 / 32)              // 222
#define NVB2  (NVB - NVB1)                 // 1350
#define PW1_BLOCKS (NVB1 * NKB)            // 2664
#define EM_BLOCKS  MTOT                    // 4096
#define BI_BLOCKS  ((VPAD + 255) / 256)    // 197
#define PREP1_GRID (PW1_BLOCKS + EM_BLOCKS + BI_BLOCKS)

#define TP 66                              // smem transpose tile pitch (conflict-free)

// Scratch (static device globals — allocation-guard safe)
__device__ __nv_bfloat16 g_wt[(size_t)VPAD * DMODEL];   // W^T [v][k], rows >= VOCAB zeroed
__device__ __nv_bfloat16 g_hid[(size_t)MTOT * DMODEL];  // hidden [m][k]
__device__ float         g_fb[VPAD];                    // float(bias), pad zeroed

// ---------------- helpers ----------------
__device__ __forceinline__ uint32_t smem_u32(const void* p) {
    return (uint32_t)__cvta_generic_to_shared(p);
}

__device__ __forceinline__ void ldsm4(uint32_t* r, uint32_t addr) {
    asm volatile("ldmatrix.sync.aligned.m8n8.x4.shared.b16 {%0,%1,%2,%3}, [%4];"
                 : "=r"(r[0]), "=r"(r[1]), "=r"(r[2]), "=r"(r[3]) : "r"(addr));
}

__device__ __forceinline__ void mma16816(float* c, const uint32_t* a, uint32_t b0, uint32_t b1) {
    asm volatile(
        "mma.sync.aligned.m16n8k16.row.col.f32.bf16.bf16.f32 "
        "{%0,%1,%2,%3}, {%4,%5,%6,%7}, {%8,%9}, {%0,%1,%2,%3};"
        : "+f"(c[0]), "+f"(c[1]), "+f"(c[2]), "+f"(c[3])
        : "r"(a[0]), "r"(a[1]), "r"(a[2]), "r"(a[3]), "r"(b0), "r"(b1));
}

__device__ __forceinline__ void cp16(uint32_t dst, const void* src) {
    asm volatile("cp.async.cg.shared.global [%0], [%1], 16;" :: "r"(dst), "l"(src));
}

// ---------------- packw tile (smem version, used in serial prep1) ----------------
__device__ __forceinline__ void packw_tile(const int* __restrict__ w, int vt, int kt) {
    __shared__ __nv_bfloat16 tile[32][TP];
    const int t  = threadIdx.x;
    const int v0 = vt * 32;
    const int k0 = kt * 64;
    const int tx = t & 31;      // v within tile
    const int ty = t >> 5;      // 0..7
    #pragma unroll
    for (int j = 0; j < 8; j++) {
        const int k = ty + 8 * j;          // 0..63
        const int v = v0 + tx;
        int val = (v < VOCAB) ? w[(size_t)(k0 + k) * VOCAB + v] : 0;
        tile[tx][k] = __float2bfloat16((float)val);
    }
    __syncthreads();
    {
        const int v  = t >> 3;            // 0..31
        const int ko = (t & 7) * 8;       // 0..56
        uint4 pkt;
        __nv_bfloat16* s = &tile[v][ko];
        pkt.x = *(const uint32_t*)(s + 0);
        pkt.y = *(const uint32_t*)(s + 2);
        pkt.z = *(const uint32_t*)(s + 4);
        pkt.w = *(const uint32_t*)(s + 6);
        *(uint4*)(g_wt + (size_t)(v0 + v) * DMODEL + k0 + ko) = pkt;
    }
}

// ---------------- prep1: packw prefix (v-tiles [0,NVB1)) + embed + bias ----------------
__global__ void __launch_bounds__(256)
prep1_kernel(const int* __restrict__ ids,
             const int* __restrict__ wte,
             const int* __restrict__ wpe,
             const int* __restrict__ w,
             const int* __restrict__ bias) {
    const int b = blockIdx.x;
    const int t = threadIdx.x;

    if (b < PW1_BLOCKS) {
        packw_tile(w, b % NVB1, b / NVB1);
    } else if (b < PW1_BLOCKS + EM_BLOCKS) {
        const int m = b - PW1_BLOCKS;          // 0..4095
        if (t < 192) {
            const int k4 = t * 4;
            const int id  = ids[m];
            const int pos = m & (SEQ - 1);
            int4 a = *(const int4*)(wte + (size_t)id  * DMODEL + k4);
            int4 p = *(const int4*)(wpe + (size_t)pos * DMODEL + k4);
            __nv_bfloat16 h[4];
            h[0] = __float2bfloat16((float)(a.x + p.x));
            h[1] = __float2bfloat16((float)(a.y + p.y));
            h[2] = __float2bfloat16((float)(a.z + p.z));
            h[3] = __float2bfloat16((float)(a.w + p.w));
            *(uint2*)(g_hid + (size_t)m * DMODEL + k4) = *(uint2*)h;
        }
    } else {
        const int i = (b - PW1_BLOCKS - EM_BLOCKS) * 256 + t;
        if (i < VPAD) g_fb[i] = (i < VOCAB) ? (float)bias[i] : 0.f;
    }
}

// ---------------- packw2_lite: co-residency-shaped background transpose ----------------
// 64 threads, ZERO smem, no barriers, ~30 regs -> fits in the slack beside
// 3 GEMM CTAs (12KB smem, ~4K regs, 52 warp slots free per SM).
// Each CTA transposes v-tile [32 rows] x full K=768. Thread t: v = v0+(t&31),
// k-half = (t>>5)*384. Reads are warp-coalesced (32 consecutive v per k);
// stores are one uint4 (16B) per 8 k.
__global__ void __launch_bounds__(64)
packw2_lite_kernel(const int* __restrict__ w) {
    const int t    = threadIdx.x;
    const int v    = (NVB1 + blockIdx.x) * 32 + (t & 31);
    const int kbeg = (t >> 5) * (DMODEL / 2);
    const bool vok = (v < VOCAB);
    __nv_bfloat16* dst = g_wt + (size_t)v * DMODEL;

    for (int kk = kbeg; kk < kbeg + DMODEL / 2; kk += 8) {
        __nv_bfloat16 h[8];
        #pragma unroll
        for (int j = 0; j < 8; j++) {
            int val = vok ? w[(size_t)(kk + j) * VOCAB + v] : 0;
            h[j] = __float2bfloat16((float)val);
        }
        *(uint4*)(dst + kk) = *(uint4*)h;
    }
}

// ---------------- main GEMM: 128x64 CTA, 4 warps of 64x32, 3 CTAs/SM ----------------
// (byte-identical core to R10..R14 — measured at the legacy mma.sync issue floor)
__global__ void __launch_bounds__(128, 3)
gemm_kernel(float* __restrict__ out, int n_base) {
    extern __shared__ unsigned char smem[];
    const int tid  = threadIdx.x;
    const int wid  = tid >> 5;
    const int lane = tid & 31;
    const int m0 = blockIdx.x * BM;
    const int n0 = (blockIdx.y + n_base) * BN;
    const int wm = (wid & 1) * 64;   // 2 warps in m
    const int wn = (wid >> 1) * 32;  // 2 warps in n

    const uint32_t sbase = smem_u32(smem);
    const __nv_bfloat16* gA = g_hid + (size_t)m0 * DMODEL;
    const __nv_bfloat16* gB = g_wt  + (size_t)n0 * DMODEL;

    int lcoA[8], lcoB[4];
    const __nv_bfloat16* lsa[8];
    const __nv_bfloat16* lsb[4];
    #pragma unroll
    for (int i = 0; i < 8; i++) {
        int idx = tid + i * 128;
        int r = idx >> 3, c = idx & 7;
        lcoA[i] = r * 128 + ((c ^ (r & 7)) << 4);
        lsa[i]  = gA + (size_t)r * DMODEL + c * 8;
    }
    #pragma unroll
    for (int i = 0; i < 4; i++) {
        int idx = tid + i * 128;
        int r = idx >> 3, c = idx & 7;
        lcoB[i] = r * 128 + ((c ^ (r & 7)) << 4);
        lsb[i]  = gB + (size_t)r * DMODEL + c * 8;
    }

    float acc[4][4][4];
    #pragma unroll
    for (int f = 0; f < 4; f++)
        #pragma unroll
        for (int j = 0; j < 4; j++)
            #pragma unroll
            for (int q = 0; q < 4; q++) acc[f][j][q] = 0.f;

    #pragma unroll
    for (int s = 0; s < STAGES - 1; s++) {
        uint32_t dstA = sbase + s * STAGE_BYTES;
        uint32_t dstB = dstA + A_TILE_BYTES;
        #pragma unroll
        for (int i = 0; i < 8; i++) cp16(dstA + lcoA[i], lsa[i] + s * BK);
        #pragma unroll
        for (int i = 0; i < 4; i++) cp16(dstB + lcoB[i], lsb[i] + s * BK);
        asm volatile("cp.async.commit_group;");
    }

    const int lrow = lane & 15;
    const int lhi  = lane >> 4;

    #pragma unroll 3
    for (int kc = 0; kc < NKC; kc++) {
        asm volatile("cp.async.wait_group %0;" :: "n"(STAGES - 2));
        __syncthreads();

        const int st = kc % STAGES;
        const uint32_t baseA = sbase + st * STAGE_BYTES;
        const uint32_t baseB = baseA + A_TILE_BYTES;

        const int nk = kc + STAGES - 1;
        if (nk < NKC) {
            const int st2 = nk % STAGES;
            uint32_t dstA = sbase + st2 * STAGE_BYTES;
            uint32_t dstB = dstA + A_TILE_BYTES;
            #pragma unroll
            for (int i = 0; i < 8; i++) cp16(dstA + lcoA[i], lsa[i] + nk * BK);
            #pragma unroll
            for (int i = 0; i < 4; i++) cp16(dstB + lcoB[i], lsb[i] + nk * BK);
        }
        asm volatile("cp.async.commit_group;");

        #pragma unroll
        for (int kk = 0; kk < 4; kk++) {
            const int c = kk * 2 + lhi;
            uint32_t a[4][4], b[2][4];
            #pragma unroll
            for (int f = 0; f < 4; f++) {
                int r = wm + f * 16 + lrow;
                ldsm4(a[f], baseA + r * 128 + ((c ^ (r & 7)) << 4));
            }
            #pragma unroll
            for (int g = 0; g < 2; g++) {
                int r = wn + g * 16 + lrow;
                ldsm4(b[g], baseB + r * 128 + ((c ^ (r & 7)) << 4));
            }
            #pragma unroll
            for (int f = 0; f < 4; f++)
                #pragma unroll
                for (int g = 0; g < 2; g++) {
                    mma16816(acc[f][2 * g + 0], a[f], b[g][0], b[g][2]);
                    mma16816(acc[f][2 * g + 1], a[f], b[g][1], b[g][3]);
                }
        }
    }

    // ---- epilogue: out = acc + float(bias); scalar 4B stores (VOCAB odd) ----
    float fb0[4], fb1[4];
    #pragma unroll
    for (int j = 0; j < 4; j++) {
        const int col = n0 + wn + j * 8 + ((lane & 3) << 1);
        fb0[j] = g_fb[col];
        fb1[j] = g_fb[col + 1 < VPAD ? col + 1 : col];
    }
    #pragma unroll
    for (int f = 0; f < 4; f++) {
        const int r = m0 + wm + f * 16 + (lane >> 2);
        float* row0 = out + (size_t)r * VOCAB;
        float* row1 = row0 + (size_t)8 * VOCAB;
        #pragma unroll
        for (int j = 0; j < 4; j++) {
            const int col = n0 + wn + j * 8 + ((lane & 3) << 1);
            if (col < VOCAB) {
                row0[col] = acc[f][j][0] + fb0[j];
                row1[col] = acc[f][j][2] + fb0[j];
            }
            if (col + 1 < VOCAB) {
                row0[col + 1] = acc[f][j][1] + fb1[j];
                row1[col + 1] = acc[f][j][3] + fb1[j];
            }
        }
    }
}

// ---------------- launch: fork co-residable packw2_lite alongside G1 ----------------
extern "C" void kernel_launch(void* const* d_in, const int* in_sizes, int n_in,
                              void* d_out, int out_size) {
    const int* ids  = (const int*)d_in[0];   // [2,2048] int32
    const int* wte  = (const int*)d_in[1];   // [50257,768] int8 widened to int32
    const int* wpe  = (const int*)d_in[2];   // [2048,768] int8 widened to int32
    const int* w    = (const int*)d_in[3];   // [768,50257] int32
    const int* bias = (const int*)d_in[4];   // [50257] int32
    float* out = (float*)d_out;              // [2,2048,50257] float32

    cudaFuncSetAttribute(gemm_kernel, cudaFuncAttributeMaxDynamicSharedMemorySize, SMEM_BYTES);

    cudaEvent_t e0, e2;
    cudaEventCreateWithFlags(&e0, cudaEventDisableTiming);
    cudaEventCreateWithFlags(&e2, cudaEventDisableTiming);

    // main stream: prep1 (embed + bias + W prefix for G1)
    prep1_kernel<<<PREP1_GRID, 256>>>(ids, wte, wpe, w, bias);
    cudaEventRecord(e0, 0);

    // fork: background transpose, shaped to co-reside in GEMM's resource slack
    cudaStreamWaitEvent(cudaStreamPerThread, e0, 0);
    packw2_lite_kernel<<<NVB2, 64, 0, cudaStreamPerThread>>>(w);
    cudaEventRecord(e2, cudaStreamPerThread);

    // G1: n-tiles [0, NT1) — needs only prep1's outputs
    gemm_kernel<<<dim3(MTOT / BM, NT1), 128, SMEM_BYTES>>>(out, 0);

    // join: G2 needs the full W^T
    cudaStreamWaitEvent(0, e2, 0);
    gemm_kernel<<<dim3(MTOT / BM, NT2), 128, SMEM_BYTES>>>(out, NT1);
}

// round 16
// speedup vs baseline: 1.0259x; 1.0259x over previous
#include <cuda_runtime.h>
#include <cuda_bf16.h>
#include <cstdint>

#define VOCAB  50257
#define VPAD   50304          // 1572 * 32, 786 * 64
#define DMODEL 768
#define MTOT   4096           // B*S
#define SEQ    2048

#define BM 128
#define BN 64
#define BK 64
#define STAGES 3
#define NKC (DMODEL / BK)                  // 12
#define A_TILE_BYTES (BM * BK * 2)         // 16384
#define B_TILE_BYTES (BN * BK * 2)         // 8192
#define STAGE_BYTES (A_TILE_BYTES + B_TILE_BYTES)  // 24576
#define SMEM_BYTES (STAGES * STAGE_BYTES)  // 73728 -> 3 CTAs/SM

// prep grid layout: packw tiles first (long pole), then embed, then bias
#define NVB (VPAD / 32)                    // 1572 v-tiles
#define NKB (DMODEL / 64)                  // 12 k-tiles
#define PW_BLOCKS (NVB * NKB)              // 18864
#define EM_BLOCKS MTOT                     // 4096
#define BI_BLOCKS ((VPAD + 255) / 256)     // 197
#define PREP_GRID (PW_BLOCKS + EM_BLOCKS + BI_BLOCKS)

#define TP 66                              // smem tile pitch (conflict-free: 33 banks/row)

// Scratch (static device globals — allocation-guard safe)
__device__ __nv_bfloat16 g_wt[(size_t)VPAD * DMODEL];   // W^T [v][k], rows >= VOCAB zeroed
__device__ __nv_bfloat16 g_hid[(size_t)MTOT * DMODEL];  // hidden [m][k]
__device__ float         g_fb[VPAD];                    // float(bias), pad zeroed

// ---------------- helpers ----------------
__device__ __forceinline__ uint32_t smem_u32(const void* p) {
    return (uint32_t)__cvta_generic_to_shared(p);
}

__device__ __forceinline__ void ldsm4(uint32_t* r, uint32_t addr) {
    asm volatile("ldmatrix.sync.aligned.m8n8.x4.shared.b16 {%0,%1,%2,%3}, [%4];"
                 : "=r"(r[0]), "=r"(r[1]), "=r"(r[2]), "=r"(r[3]) : "r"(addr));
}

__device__ __forceinline__ void mma16816(float* c, const uint32_t* a, uint32_t b0, uint32_t b1) {
    asm volatile(
        "mma.sync.aligned.m16n8k16.row.col.f32.bf16.bf16.f32 "
        "{%0,%1,%2,%3}, {%4,%5,%6,%7}, {%8,%9}, {%0,%1,%2,%3};"
        : "+f"(c[0]), "+f"(c[1]), "+f"(c[2]), "+f"(c[3])
        : "r"(a[0]), "r"(a[1]), "r"(a[2]), "r"(a[3]), "r"(b0), "r"(b1));
}

__device__ __forceinline__ void cp16(uint32_t dst, const void* src) {
    asm volatile("cp.async.cg.shared.global [%0], [%1], 16;" :: "r"(dst), "l"(src));
}

// ---------------- fused prep: W^T transpose (16B stores) + embed + bias ----------------
// wte/wpe/w arrive as int32 (harness widens int8 inputs).
__global__ void __launch_bounds__(256)
prep_kernel(const int* __restrict__ ids,
            const int* __restrict__ wte,
            const int* __restrict__ wpe,
            const int* __restrict__ w,
            const int* __restrict__ bias) {
    __shared__ __nv_bfloat16 tile[32][TP];
    const int b = blockIdx.x;
    const int t = threadIdx.x;

    if (b < PW_BLOCKS) {
        // --- packw tile: 32 v x 64 k ---
        const int v0 = (b % NVB) * 32;
        const int k0 = (b / NVB) * 64;
        const int tx = t & 31;      // v within tile
        const int ty = t >> 5;      // 0..7
        // load: warp reads 32 consecutive v for one k row (128B coalesced)
        #pragma unroll
        for (int j = 0; j < 8; j++) {
            const int k = ty + 8 * j;          // 0..63
            const int v = v0 + tx;
            int val = (v < VOCAB) ? w[(size_t)(k0 + k) * VOCAB + v] : 0;
            tile[tx][k] = __float2bfloat16((float)val);
        }
        __syncthreads();
        // store: each thread 8 contiguous bf16 (16B) -> 4 x 128B segments per warp
        {
            const int v  = t >> 3;            // 0..31
            const int ko = (t & 7) * 8;       // 0..56
            uint4 pkt;
            __nv_bfloat16* s = &tile[v][ko];
            pkt.x = *(const uint32_t*)(s + 0);
            pkt.y = *(const uint32_t*)(s + 2);
            pkt.z = *(const uint32_t*)(s + 4);
            pkt.w = *(const uint32_t*)(s + 6);
            *(uint4*)(g_wt + (size_t)(v0 + v) * DMODEL + k0 + ko) = pkt;
        }
    } else if (b < PW_BLOCKS + EM_BLOCKS) {
        // --- embed: hidden = bf16(wte[id] + wpe[pos]) ---
        const int m = b - PW_BLOCKS;          // 0..4095
        if (t < 192) {
            const int k4 = t * 4;
            const int id  = ids[m];
            const int pos = m & (SEQ - 1);
            int4 a = *(const int4*)(wte + (size_t)id  * DMODEL + k4);
            int4 p = *(const int4*)(wpe + (size_t)pos * DMODEL + k4);
            __nv_bfloat16 h[4];
            h[0] = __float2bfloat16((float)(a.x + p.x));
            h[1] = __float2bfloat16((float)(a.y + p.y));
            h[2] = __float2bfloat16((float)(a.z + p.z));
            h[3] = __float2bfloat16((float)(a.w + p.w));
            *(uint2*)(g_hid + (size_t)m * DMODEL + k4) = *(uint2*)h;
        }
    } else {
        // --- bias -> float table, pad zeroed ---
        const int i = (b - PW_BLOCKS - EM_BLOCKS) * 256 + t;
        if (i < VPAD) g_fb[i] = (i < VOCAB) ? (float)bias[i] : 0.f;
    }
}

// ---------------- main GEMM: 128x64 CTA, 4 warps of 64x32, 3 CTAs/SM ----------------
// Measured at the legacy mma.sync issue floor (rt = 16 cyc/HMMA/SMSP).
__global__ void __launch_bounds__(128, 3)
gemm_kernel(float* __restrict__ out) {
    extern __shared__ unsigned char smem[];
    const int tid  = threadIdx.x;
    const int wid  = tid >> 5;
    const int lane = tid & 31;
    const int m0 = blockIdx.x * BM;
    const int n0 = blockIdx.y * BN;
    const int wm = (wid & 1) * 64;   // 2 warps in m
    const int wn = (wid >> 1) * 32;  // 2 warps in n

    const uint32_t sbase = smem_u32(smem);
    const __nv_bfloat16* gA = g_hid + (size_t)m0 * DMODEL;
    const __nv_bfloat16* gB = g_wt  + (size_t)n0 * DMODEL;

    int lcoA[8], lcoB[4];
    const __nv_bfloat16* lsa[8];
    const __nv_bfloat16* lsb[4];
    #pragma unroll
    for (int i = 0; i < 8; i++) {
        int idx = tid + i * 128;
        int r = idx >> 3, c = idx & 7;
        lcoA[i] = r * 128 + ((c ^ (r & 7)) << 4);
        lsa[i]  = gA + (size_t)r * DMODEL + c * 8;
    }
    #pragma unroll
    for (int i = 0; i < 4; i++) {
        int idx = tid + i * 128;
        int r = idx >> 3, c = idx & 7;
        lcoB[i] = r * 128 + ((c ^ (r & 7)) << 4);
        lsb[i]  = gB + (size_t)r * DMODEL + c * 8;
    }

    float acc[4][4][4];
    #pragma unroll
    for (int f = 0; f < 4; f++)
        #pragma unroll
        for (int j = 0; j < 4; j++)
            #pragma unroll
            for (int q = 0; q < 4; q++) acc[f][j][q] = 0.f;

    #pragma unroll
    for (int s = 0; s < STAGES - 1; s++) {
        uint32_t dstA = sbase + s * STAGE_BYTES;
        uint32_t dstB = dstA + A_TILE_BYTES;
        #pragma unroll
        for (int i = 0; i < 8; i++) cp16(dstA + lcoA[i], lsa[i] + s * BK);
        #pragma unroll
        for (int i = 0; i < 4; i++) cp16(dstB + lcoB[i], lsb[i] + s * BK);
        asm volatile("cp.async.commit_group;");
    }

    const int lrow = lane & 15;
    const int lhi  = lane >> 4;

    #pragma unroll 3
    for (int kc = 0; kc < NKC; kc++) {
        asm volatile("cp.async.wait_group %0;" :: "n"(STAGES - 2));
        __syncthreads();

        const int st = kc % STAGES;
        const uint32_t baseA = sbase + st * STAGE_BYTES;
        const uint32_t baseB = baseA + A_TILE_BYTES;

        const int nk = kc + STAGES - 1;
        if (nk < NKC) {
            const int st2 = nk % STAGES;
            uint32_t dstA = sbase + st2 * STAGE_BYTES;
            uint32_t dstB = dstA + A_TILE_BYTES;
            #pragma unroll
            for (int i = 0; i < 8; i++) cp16(dstA + lcoA[i], lsa[i] + nk * BK);
            #pragma unroll
            for (int i = 0; i < 4; i++) cp16(dstB + lcoB[i], lsb[i] + nk * BK);
        }
        asm volatile("cp.async.commit_group;");

        #pragma unroll
        for (int kk = 0; kk < 4; kk++) {
            const int c = kk * 2 + lhi;
            uint32_t a[4][4], b[2][4];
            #pragma unroll
            for (int f = 0; f < 4; f++) {
                int r = wm + f * 16 + lrow;
                ldsm4(a[f], baseA + r * 128 + ((c ^ (r & 7)) << 4));
            }
            #pragma unroll
            for (int g = 0; g < 2; g++) {
                int r = wn + g * 16 + lrow;
                ldsm4(b[g], baseB + r * 128 + ((c ^ (r & 7)) << 4));
            }
            #pragma unroll
            for (int f = 0; f < 4; f++)
                #pragma unroll
                for (int g = 0; g < 2; g++) {
                    mma16816(acc[f][2 * g + 0], a[f], b[g][0], b[g][2]);
                    mma16816(acc[f][2 * g + 1], a[f], b[g][1], b[g][3]);
                }
        }
    }

    // ---- epilogue: out = acc + float(bias); scalar 4B stores (VOCAB odd) ----
    float fb0[4], fb1[4];
    #pragma unroll
    for (int j = 0; j < 4; j++) {
        const int col = n0 + wn + j * 8 + ((lane & 3) << 1);
        fb0[j] = g_fb[col];
        fb1[j] = g_fb[col + 1 < VPAD ? col + 1 : col];
    }
    #pragma unroll
    for (int f = 0; f < 4; f++) {
        const int r = m0 + wm + f * 16 + (lane >> 2);
        float* row0 = out + (size_t)r * VOCAB;
        float* row1 = row0 + (size_t)8 * VOCAB;
        #pragma unroll
        for (int j = 0; j < 4; j++) {
            const int col = n0 + wn + j * 8 + ((lane & 3) << 1);
            if (col < VOCAB) {
                row0[col] = acc[f][j][0] + fb0[j];
                row1[col] = acc[f][j][2] + fb0[j];
            }
            if (col + 1 < VOCAB) {
                row0[col + 1] = acc[f][j][1] + fb1[j];
                row1[col + 1] = acc[f][j][3] + fb1[j];
            }
        }
    }
}

// ---------------- launch ----------------
extern "C" void kernel_launch(void* const* d_in, const int* in_sizes, int n_in,
                              void* d_out, int out_size) {
    const int* ids  = (const int*)d_in[0];   // [2,2048] int32
    const int* wte  = (const int*)d_in[1];   // [50257,768] int8 widened to int32
    const int* wpe  = (const int*)d_in[2];   // [2048,768] int8 widened to int32
    const int* w    = (const int*)d_in[3];   // [768,50257] int32
    const int* bias = (const int*)d_in[4];   // [50257] int32
    float* out = (float*)d_out;              // [2,2048,50257] float32

    cudaFuncSetAttribute(gemm_kernel, cudaFuncAttributeMaxDynamicSharedMemorySize, SMEM_BYTES);

    prep_kernel<<<PREP_GRID, 256>>>(ids, wte, wpe, w, bias);
    gemm_kernel<<<dim3(MTOT / BM, VPAD / BN), 128, SMEM_BYTES>>>(out);
}